// round 3
// baseline (speedup 1.0000x reference)
#include <cuda_runtime.h>
#include <cstdint>

#define Hdim   1024
#define Edim   16
#define FFdim  1024
#define FF2dim 2048
#define Stok   2048
#define NPAIR  8192
#define CLIPV  7.0f
#define APAD   68   // padded sA row (floats): 272B, 16B-aligned, kills 16-way STS conflict

// ---------------- device scratch (static, allowed) ----------------
__device__ int   g_cnt[Edim];
__device__ int   g_off[Edim];
__device__ int   g_btok[Edim][Stok];
__device__ float g_bw[Edim][Stok];
__device__ float g_imp[4];
__device__ int   g_load[4];
__device__ float g_h[(size_t)NPAIR * FF2dim];   // 64 MB
__device__ float g_act[(size_t)NPAIR * FFdim];  // 32 MB

// ---------------- packed fp32x2 helpers (Blackwell) ----------------
#define FMA2(d, a, b) asm("fma.rn.f32x2 %0, %1, %2, %0;" : "+l"(d) : "l"(a), "l"(b))
#define PACK2(d, s)   asm("mov.b64 %0, {%1, %1};" : "=l"(d) : "f"(s))

__device__ __forceinline__ float lo32(unsigned long long v) {
    return __uint_as_float((unsigned)(v & 0xffffffffu));
}
__device__ __forceinline__ float hi32(unsigned long long v) {
    return __uint_as_float((unsigned)(v >> 32));
}

// ---------------- kernel 1: zero output + counters ----------------
__global__ void k_zero(float* __restrict__ out, int out_size) {
    int stride = gridDim.x * blockDim.x;
    for (int i = blockIdx.x * blockDim.x + threadIdx.x; i < out_size; i += stride)
        out[i] = 0.0f;
    if (blockIdx.x == 0) {
        int t = threadIdx.x;
        if (t < Edim) g_cnt[t] = 0;
        if (t < 4) { g_imp[t] = 0.0f; g_load[t] = 0; }
    }
}

// ---------------- kernel 2: router ----------------
__global__ void k_router(const float* __restrict__ x,
                         const float* __restrict__ rw,
                         const float* __restrict__ rb) {
    int s = blockIdx.x;
    __shared__ float xs[Hdim];
    __shared__ float lg[Edim];
    int tid = threadIdx.x;
    for (int i = tid; i < Hdim; i += 128) xs[i] = x[(size_t)s * Hdim + i];
    __syncthreads();

    int warp = tid >> 5, lane = tid & 31;
    for (int e = warp; e < Edim; e += 4) {
        const float* w = rw + (size_t)e * Hdim;
        float p = 0.0f;
        for (int h = lane; h < Hdim; h += 32) p += xs[h] * w[h];
        #pragma unroll
        for (int o = 16; o > 0; o >>= 1) p += __shfl_down_sync(0xffffffffu, p, o);
        if (lane == 0) lg[e] = p + rb[e];
    }
    __syncthreads();

    if (tid == 0) {
        float l[Edim];
        #pragma unroll
        for (int e = 0; e < Edim; e++) l[e] = lg[e];
        int idx[4]; float val[4];
        bool used[Edim] = {};
        for (int k = 0; k < 4; k++) {                 // top-4, ties -> lowest index
            int bi = 0; float bv = -1e30f;
            for (int e = 0; e < Edim; e++)
                if (!used[e] && l[e] > bv) { bv = l[e]; bi = e; }
            used[bi] = true; idx[k] = bi; val[k] = bv;
        }
        // softmax over top-4 (val[0] is the global max)
        float m = val[0], w4[4], sum = 0.0f;
        #pragma unroll
        for (int k = 0; k < 4; k++) { w4[k] = expf(val[k] - m); sum += w4[k]; }
        #pragma unroll
        for (int k = 0; k < 4; k++) w4[k] /= sum;
        // full softmax -> importance (only experts 0..3 matter: load one-hot lands in 0..3)
        float den = 0.0f;
        for (int e = 0; e < Edim; e++) den += expf(l[e] - m);
        #pragma unroll
        for (int p = 0; p < 4; p++) atomicAdd(&g_imp[p], expf(l[p] - m) / den);
        // load: one_hot of argmax POSITION within the top-k index vector (reference quirk)
        int bp = 0, bidx = idx[0];
        #pragma unroll
        for (int k = 1; k < 4; k++) if (idx[k] > bidx) { bidx = idx[k]; bp = k; }
        atomicAdd(&g_load[bp], 1);
        // bucket insert
        #pragma unroll
        for (int k = 0; k < 4; k++) {
            int e = idx[k];
            int pos = atomicAdd(&g_cnt[e], 1);
            g_btok[e][pos] = s;
            g_bw[e][pos]   = w4[k];
        }
    }
}

// ---------------- kernel 3: expert offsets + aux loss ----------------
__global__ void k_offsets(float* __restrict__ out, int out_size) {
    if (threadIdx.x == 0 && blockIdx.x == 0) {
        int off = 0;
        for (int e = 0; e < Edim; e++) { g_off[e] = off; off += g_cnt[e]; }
        float aux = 0.0f;
        for (int p = 0; p < 4; p++)
            aux += (g_imp[p] / (float)Stok) * ((float)g_load[p] / (float)Stok);
        aux *= 0.02f * (float)Edim;
        if (out_size > Stok * Hdim) out[Stok * Hdim] = aux;
    }
}

// ---------------- kernel 4: GEMM1  h = gather(x) @ W_in[e] + b_in[e] ----------------
__global__ __launch_bounds__(128) void k_gemm1(const float* __restrict__ x,
                                               const float* __restrict__ W_in,
                                               const float* __restrict__ b_in) {
    int e = blockIdx.z;
    int cnt = g_cnt[e];
    int m0 = blockIdx.y * 64;
    if (m0 >= cnt) return;
    int n0 = blockIdx.x * 128;

    __shared__ __align__(16) float sA[2][16][APAD];
    __shared__ __align__(16) float sB[2][16][128];
    __shared__ int stok[64];

    int tid = threadIdx.x;
    if (tid < 64) {
        int r = m0 + tid;
        stok[tid] = g_btok[e][r < cnt ? r : 0];
    }
    __syncthreads();

    const float* Bp = W_in + (size_t)e * Hdim * FF2dim + n0;
    int tx = tid & 15, ty = tid >> 4;

    unsigned long long acc[8][4];
    #pragma unroll
    for (int i = 0; i < 8; i++)
        #pragma unroll
        for (int j = 0; j < 4; j++) acc[i][j] = 0ull;

    // prologue: stage 0
    #pragma unroll
    for (int j = 0; j < 8; j++) {
        int i = tid + j * 128; int m = i >> 4, k = i & 15;
        sA[0][k][m] = x[(size_t)stok[m] * Hdim + k];
    }
    #pragma unroll
    for (int j = 0; j < 16; j++) {
        int i = tid + j * 128; int k = i >> 7, n = i & 127;
        sB[0][k][n] = Bp[(size_t)k * FF2dim + n];
    }
    __syncthreads();

    float rA[8], rB[16];
    const int nK = Hdim / 16;
    for (int kt = 0; kt < nK; kt++) {
        int buf = kt & 1;
        if (kt + 1 < nK) {
            int kb = (kt + 1) * 16;
            #pragma unroll
            for (int j = 0; j < 8; j++) {
                int i = tid + j * 128; int m = i >> 4, k = i & 15;
                rA[j] = x[(size_t)stok[m] * Hdim + kb + k];
            }
            #pragma unroll
            for (int j = 0; j < 16; j++) {
                int i = tid + j * 128; int k = i >> 7, n = i & 127;
                rB[j] = Bp[(size_t)(kb + k) * FF2dim + n];
            }
        }
        #pragma unroll
        for (int k = 0; k < 16; k++) {
            float4 a0 = *(const float4*)&sA[buf][k][ty * 8];
            float4 a1 = *(const float4*)&sA[buf][k][ty * 8 + 4];
            unsigned long long bp[4];
            #pragma unroll
            for (int j = 0; j < 4; j++)
                bp[j] = *(const unsigned long long*)&sB[buf][k][tx * 8 + 2 * j];
            float av[8] = {a0.x, a0.y, a0.z, a0.w, a1.x, a1.y, a1.z, a1.w};
            #pragma unroll
            for (int i = 0; i < 8; i++) {
                unsigned long long ap; PACK2(ap, av[i]);
                #pragma unroll
                for (int j = 0; j < 4; j++) FMA2(acc[i][j], ap, bp[j]);
            }
        }
        if (kt + 1 < nK) {
            int nb = buf ^ 1;
            #pragma unroll
            for (int j = 0; j < 8; j++) {
                int i = tid + j * 128; int m = i >> 4, k = i & 15;
                sA[nb][k][m] = rA[j];
            }
            #pragma unroll
            for (int j = 0; j < 16; j++) {
                int i = tid + j * 128; int k = i >> 7, n = i & 127;
                sB[nb][k][n] = rB[j];
            }
        }
        __syncthreads();
    }

    int off = g_off[e];
    const float* bi = b_in + (size_t)e * FF2dim + n0 + tx * 8;
    #pragma unroll
    for (int i = 0; i < 8; i++) {
        int r = m0 + ty * 8 + i;
        if (r < cnt) {
            float* dst = g_h + (size_t)(off + r) * FF2dim + n0 + tx * 8;
            #pragma unroll
            for (int j = 0; j < 4; j++) {
                dst[2 * j]     = lo32(acc[i][j]) + bi[2 * j];
                dst[2 * j + 1] = hi32(acc[i][j]) + bi[2 * j + 1];
            }
        }
    }
}

// ---------------- kernel 5: clip + SiLU gate ----------------
__global__ void k_act() {
    int stride = gridDim.x * blockDim.x;
    for (int idx = blockIdx.x * blockDim.x + threadIdx.x;
         idx < NPAIR * FFdim; idx += stride) {
        int p = idx >> 10, f = idx & 1023;
        float up   = g_h[(size_t)p * FF2dim + f];
        float gate = g_h[(size_t)p * FF2dim + FFdim + f];
        up   = fminf(fmaxf(up,   -CLIPV), CLIPV);
        gate = fminf(fmaxf(gate, -CLIPV), CLIPV);
        float sg = gate / (1.0f + expf(-gate));
        g_act[(size_t)p * FFdim + f] = sg * up;
    }
}

// ---------------- kernel 6: GEMM2  out += w * (act @ W_out[e] + b_out[e]) ----------------
__global__ __launch_bounds__(128) void k_gemm2(const float* __restrict__ W_out,
                                               const float* __restrict__ b_out,
                                               float* __restrict__ out) {
    int e = blockIdx.z;
    int cnt = g_cnt[e];
    int m0 = blockIdx.y * 64;
    if (m0 >= cnt) return;
    int n0 = blockIdx.x * 128;

    __shared__ __align__(16) float sA[2][16][APAD];
    __shared__ __align__(16) float sB[2][16][128];
    __shared__ int   stok[64];
    __shared__ float swt[64];

    int tid = threadIdx.x;
    int off = g_off[e];
    if (tid < 64) {
        int r = m0 + tid;
        int rr = r < cnt ? r : 0;
        stok[tid] = g_btok[e][rr];
        swt[tid]  = g_bw[e][rr];
    }
    __syncthreads();

    const float* Ap = g_act + (size_t)off * FFdim;
    const float* Bp = W_out + (size_t)e * FFdim * Hdim + n0;
    int tx = tid & 15, ty = tid >> 4;

    unsigned long long acc[8][4];
    #pragma unroll
    for (int i = 0; i < 8; i++)
        #pragma unroll
        for (int j = 0; j < 4; j++) acc[i][j] = 0ull;

    #pragma unroll
    for (int j = 0; j < 8; j++) {
        int i = tid + j * 128; int m = i >> 4, k = i & 15;
        int mm = (m0 + m < cnt) ? (m0 + m) : 0;
        sA[0][k][m] = Ap[(size_t)mm * FFdim + k];
    }
    #pragma unroll
    for (int j = 0; j < 16; j++) {
        int i = tid + j * 128; int k = i >> 7, n = i & 127;
        sB[0][k][n] = Bp[(size_t)k * Hdim + n];
    }
    __syncthreads();

    float rA[8], rB[16];
    const int nK = FFdim / 16;
    for (int kt = 0; kt < nK; kt++) {
        int buf = kt & 1;
        if (kt + 1 < nK) {
            int kb = (kt + 1) * 16;
            #pragma unroll
            for (int j = 0; j < 8; j++) {
                int i = tid + j * 128; int m = i >> 4, k = i & 15;
                int mm = (m0 + m < cnt) ? (m0 + m) : 0;
                rA[j] = Ap[(size_t)mm * FFdim + kb + k];
            }
            #pragma unroll
            for (int j = 0; j < 16; j++) {
                int i = tid + j * 128; int k = i >> 7, n = i & 127;
                rB[j] = Bp[(size_t)(kb + k) * Hdim + n];
            }
        }
        #pragma unroll
        for (int k = 0; k < 16; k++) {
            float4 a0 = *(const float4*)&sA[buf][k][ty * 8];
            float4 a1 = *(const float4*)&sA[buf][k][ty * 8 + 4];
            unsigned long long bp[4];
            #pragma unroll
            for (int j = 0; j < 4; j++)
                bp[j] = *(const unsigned long long*)&sB[buf][k][tx * 8 + 2 * j];
            float av[8] = {a0.x, a0.y, a0.z, a0.w, a1.x, a1.y, a1.z, a1.w};
            #pragma unroll
            for (int i = 0; i < 8; i++) {
                unsigned long long ap; PACK2(ap, av[i]);
                #pragma unroll
                for (int j = 0; j < 4; j++) FMA2(acc[i][j], ap, bp[j]);
            }
        }
        if (kt + 1 < nK) {
            int nb = buf ^ 1;
            #pragma unroll
            for (int j = 0; j < 8; j++) {
                int i = tid + j * 128; int m = i >> 4, k = i & 15;
                sA[nb][k][m] = rA[j];
            }
            #pragma unroll
            for (int j = 0; j < 16; j++) {
                int i = tid + j * 128; int k = i >> 7, n = i & 127;
                sB[nb][k][n] = rB[j];
            }
        }
        __syncthreads();
    }

    const float* bo = b_out + (size_t)e * Hdim + n0 + tx * 8;
    #pragma unroll
    for (int i = 0; i < 8; i++) {
        int r = m0 + ty * 8 + i;
        if (r < cnt) {
            int tok = stok[ty * 8 + i];
            float w = swt[ty * 8 + i];
            float* dst = out + (size_t)tok * Hdim + n0 + tx * 8;
            #pragma unroll
            for (int j = 0; j < 4; j++) {
                atomicAdd(&dst[2 * j],     (lo32(acc[i][j]) + bo[2 * j]) * w);
                atomicAdd(&dst[2 * j + 1], (hi32(acc[i][j]) + bo[2 * j + 1]) * w);
            }
        }
    }
}

// ---------------- launcher ----------------
extern "C" void kernel_launch(void* const* d_in, const int* in_sizes, int n_in,
                              void* d_out, int out_size) {
    const float* x     = (const float*)d_in[0];
    const float* W_in  = (const float*)d_in[1];
    const float* b_in  = (const float*)d_in[2];
    const float* W_out = (const float*)d_in[3];
    const float* b_out = (const float*)d_in[4];
    const float* rw    = (const float*)d_in[5];
    const float* rb    = (const float*)d_in[6];
    float* out = (float*)d_out;

    k_zero<<<512, 256>>>(out, out_size);
    k_router<<<Stok, 128>>>(x, rw, rb);
    k_offsets<<<1, 32>>>(out, out_size);
    k_gemm1<<<dim3(FF2dim / 128, Stok / 64, Edim), 128>>>(x, W_in, b_in);
    k_act<<<2048, 256>>>();
    k_gemm2<<<dim3(Hdim / 128, Stok / 64, Edim), 128>>>(W_out, b_out, out);
}

// round 6
// speedup vs baseline: 1.1515x; 1.1515x over previous
#include <cuda_runtime.h>
#include <cstdint>

#define Hdim   1024
#define Edim   16
#define FFdim  1024
#define FF2dim 2048
#define Stok   2048
#define NPAIR  8192
#define CLIPV  7.0f
#define APAD   68   // padded sA row (floats): kills 16-way STS conflict on A staging

// ---------------- device scratch (static, allowed) ----------------
__device__ int   g_cnt[Edim];
__device__ int   g_off[Edim];
__device__ int   g_btok[Edim][Stok];
__device__ float g_bw[Edim][Stok];
__device__ float g_imp[4];
__device__ int   g_load[4];
__device__ float g_h[(size_t)NPAIR * FF2dim];   // 64 MB
__device__ float g_act[(size_t)NPAIR * FFdim];  // 32 MB

// ---------------- packed fp32x2 helpers (Blackwell) ----------------
#define FMA2(d, a, b) asm("fma.rn.f32x2 %0, %1, %2, %0;" : "+l"(d) : "l"(a), "l"(b))
#define PACK2(d, s)   asm("mov.b64 %0, {%1, %1};" : "=l"(d) : "f"(s))

__device__ __forceinline__ float lo32(unsigned long long v) {
    return __uint_as_float((unsigned)(v & 0xffffffffu));
}
__device__ __forceinline__ float hi32(unsigned long long v) {
    return __uint_as_float((unsigned)(v >> 32));
}

// ---------------- kernel 1: zero output + counters ----------------
__global__ void k_zero(float* __restrict__ out, int out_size) {
    int stride = gridDim.x * blockDim.x;
    for (int i = blockIdx.x * blockDim.x + threadIdx.x; i < out_size; i += stride)
        out[i] = 0.0f;
    if (blockIdx.x == 0) {
        int t = threadIdx.x;
        if (t < Edim) g_cnt[t] = 0;
        if (t < 4) { g_imp[t] = 0.0f; g_load[t] = 0; }
    }
}

// ---------------- kernel 2: router ----------------
__global__ void k_router(const float* __restrict__ x,
                         const float* __restrict__ rw,
                         const float* __restrict__ rb) {
    int s = blockIdx.x;
    __shared__ float xs[Hdim];
    __shared__ float lg[Edim];
    int tid = threadIdx.x;
    for (int i = tid; i < Hdim; i += 128) xs[i] = x[(size_t)s * Hdim + i];
    __syncthreads();

    int warp = tid >> 5, lane = tid & 31;
    for (int e = warp; e < Edim; e += 4) {
        const float* w = rw + (size_t)e * Hdim;
        float p = 0.0f;
        for (int h = lane; h < Hdim; h += 32) p += xs[h] * w[h];
        #pragma unroll
        for (int o = 16; o > 0; o >>= 1) p += __shfl_down_sync(0xffffffffu, p, o);
        if (lane == 0) lg[e] = p + rb[e];
    }
    __syncthreads();

    if (tid == 0) {
        float l[Edim];
        #pragma unroll
        for (int e = 0; e < Edim; e++) l[e] = lg[e];
        int idx[4]; float val[4];
        bool used[Edim] = {};
        for (int k = 0; k < 4; k++) {                 // top-4, ties -> lowest index
            int bi = 0; float bv = -1e30f;
            for (int e = 0; e < Edim; e++)
                if (!used[e] && l[e] > bv) { bv = l[e]; bi = e; }
            used[bi] = true; idx[k] = bi; val[k] = bv;
        }
        // softmax over top-4 (val[0] is the global max)
        float m = val[0], w4[4], sum = 0.0f;
        #pragma unroll
        for (int k = 0; k < 4; k++) { w4[k] = expf(val[k] - m); sum += w4[k]; }
        #pragma unroll
        for (int k = 0; k < 4; k++) w4[k] /= sum;
        // full softmax -> importance (only experts 0..3 matter for the aux product)
        float den = 0.0f;
        for (int e = 0; e < Edim; e++) den += expf(l[e] - m);
        #pragma unroll
        for (int p = 0; p < 4; p++) atomicAdd(&g_imp[p], expf(l[p] - m) / den);
        // load: one_hot of argmax POSITION within the top-k index vector (reference quirk)
        int bp = 0, bidx = idx[0];
        #pragma unroll
        for (int k = 1; k < 4; k++) if (idx[k] > bidx) { bidx = idx[k]; bp = k; }
        atomicAdd(&g_load[bp], 1);
        // bucket insert
        #pragma unroll
        for (int k = 0; k < 4; k++) {
            int e = idx[k];
            int pos = atomicAdd(&g_cnt[e], 1);
            g_btok[e][pos] = s;
            g_bw[e][pos]   = w4[k];
        }
    }
}

// ---------------- kernel 3: expert offsets + aux loss ----------------
__global__ void k_offsets(float* __restrict__ out, int out_size) {
    if (threadIdx.x == 0 && blockIdx.x == 0) {
        int off = 0;
        for (int e = 0; e < Edim; e++) { g_off[e] = off; off += g_cnt[e]; }
        float aux = 0.0f;
        for (int p = 0; p < 4; p++)
            aux += (g_imp[p] / (float)Stok) * ((float)g_load[p] / (float)Stok);
        aux *= 0.02f * (float)Edim;
        if (out_size > Stok * Hdim) out[Stok * Hdim] = aux;
    }
}

// =====================================================================
// GEMM core notes:
//  - 64x128 block tile, TK=16, 128 threads, 8x8 per-thread micro-tile.
//  - Thread columns are SPLIT-HALF: {tx*4..tx*4+3} and {64+tx*4..+3} so
//    fragment loads are 2x LDS.128 at 16B lane stride -> conflict-free.
//  - acc[i][0..1] = first half pair-cols, acc[i][2..3] = second half.
// =====================================================================

// ---------------- kernel 4: GEMM1  h = gather(x) @ W_in[e] + b_in[e] ----------------
__global__ __launch_bounds__(128) void k_gemm1(const float* __restrict__ x,
                                               const float* __restrict__ W_in,
                                               const float* __restrict__ b_in) {
    int e = blockIdx.z;
    int cnt = g_cnt[e];
    int m0 = blockIdx.y * 64;
    if (m0 >= cnt) return;
    int n0 = blockIdx.x * 128;

    __shared__ __align__(16) float sA[2][16][APAD];
    __shared__ __align__(16) float sB[2][16][128];
    __shared__ int stok[64];

    int tid = threadIdx.x;
    if (tid < 64) {
        int r = m0 + tid;
        stok[tid] = g_btok[e][r < cnt ? r : 0];
    }
    __syncthreads();

    const float* Bp = W_in + (size_t)e * Hdim * FF2dim + n0;
    int tx = tid & 15, ty = tid >> 4;

    unsigned long long acc[8][4];
    #pragma unroll
    for (int i = 0; i < 8; i++)
        #pragma unroll
        for (int j = 0; j < 4; j++) acc[i][j] = 0ull;

    // prologue: stage 0
    #pragma unroll
    for (int j = 0; j < 8; j++) {
        int i = tid + j * 128; int m = i >> 4, k = i & 15;
        sA[0][k][m] = x[(size_t)stok[m] * Hdim + k];
    }
    #pragma unroll
    for (int j = 0; j < 4; j++) {
        int c = tid + j * 128; int k = c >> 5, n4 = c & 31;
        *(float4*)&sB[0][k][n4 * 4] =
            *(const float4*)&Bp[(size_t)k * FF2dim + n4 * 4];
    }
    __syncthreads();

    float rA[8]; float4 rB[4];
    const int nK = Hdim / 16;
    for (int kt = 0; kt < nK; kt++) {
        int buf = kt & 1;
        if (kt + 1 < nK) {
            int kb = (kt + 1) * 16;
            #pragma unroll
            for (int j = 0; j < 8; j++) {
                int i = tid + j * 128; int m = i >> 4, k = i & 15;
                rA[j] = x[(size_t)stok[m] * Hdim + kb + k];
            }
            #pragma unroll
            for (int j = 0; j < 4; j++) {
                int c = tid + j * 128; int k = c >> 5, n4 = c & 31;
                rB[j] = *(const float4*)&Bp[(size_t)(kb + k) * FF2dim + n4 * 4];
            }
        }
        #pragma unroll
        for (int k = 0; k < 16; k++) {
            float4 a0 = *(const float4*)&sA[buf][k][ty * 8];
            float4 a1 = *(const float4*)&sA[buf][k][ty * 8 + 4];
            ulonglong2 b0 = *(const ulonglong2*)&sB[buf][k][tx * 4];
            ulonglong2 b1 = *(const ulonglong2*)&sB[buf][k][64 + tx * 4];
            unsigned long long bp[4] = {b0.x, b0.y, b1.x, b1.y};
            float av[8] = {a0.x, a0.y, a0.z, a0.w, a1.x, a1.y, a1.z, a1.w};
            #pragma unroll
            for (int i = 0; i < 8; i++) {
                unsigned long long ap; PACK2(ap, av[i]);
                #pragma unroll
                for (int j = 0; j < 4; j++) FMA2(acc[i][j], ap, bp[j]);
            }
        }
        if (kt + 1 < nK) {
            int nb = buf ^ 1;
            #pragma unroll
            for (int j = 0; j < 8; j++) {
                int i = tid + j * 128; int m = i >> 4, k = i & 15;
                sA[nb][k][m] = rA[j];
            }
            #pragma unroll
            for (int j = 0; j < 4; j++) {
                int c = tid + j * 128; int k = c >> 5, n4 = c & 31;
                *(float4*)&sB[nb][k][n4 * 4] = rB[j];
            }
        }
        __syncthreads();
    }

    int off = g_off[e];
    const float* bi0 = b_in + (size_t)e * FF2dim + n0 + tx * 4;
    const float* bi1 = bi0 + 64;
    #pragma unroll
    for (int i = 0; i < 8; i++) {
        int r = m0 + ty * 8 + i;
        if (r < cnt) {
            float* dst = g_h + (size_t)(off + r) * FF2dim + n0;
            float4 v0, v1;
            v0.x = lo32(acc[i][0]) + bi0[0];
            v0.y = hi32(acc[i][0]) + bi0[1];
            v0.z = lo32(acc[i][1]) + bi0[2];
            v0.w = hi32(acc[i][1]) + bi0[3];
            v1.x = lo32(acc[i][2]) + bi1[0];
            v1.y = hi32(acc[i][2]) + bi1[1];
            v1.z = lo32(acc[i][3]) + bi1[2];
            v1.w = hi32(acc[i][3]) + bi1[3];
            *(float4*)&dst[tx * 4]      = v0;
            *(float4*)&dst[64 + tx * 4] = v1;
        }
    }
}

// ---------------- kernel 5: clip + SiLU gate ----------------
__global__ void k_act() {
    int stride = gridDim.x * blockDim.x;
    for (int idx = blockIdx.x * blockDim.x + threadIdx.x;
         idx < NPAIR * FFdim; idx += stride) {
        int p = idx >> 10, f = idx & 1023;
        float up   = g_h[(size_t)p * FF2dim + f];
        float gate = g_h[(size_t)p * FF2dim + FFdim + f];
        up   = fminf(fmaxf(up,   -CLIPV), CLIPV);
        gate = fminf(fmaxf(gate, -CLIPV), CLIPV);
        float sg = gate / (1.0f + expf(-gate));
        g_act[(size_t)p * FFdim + f] = sg * up;
    }
}

// ---------------- kernel 6: GEMM2  out += w * (act @ W_out[e] + b_out[e]) ----------------
__global__ __launch_bounds__(128) void k_gemm2(const float* __restrict__ W_out,
                                               const float* __restrict__ b_out,
                                               float* __restrict__ out) {
    int e = blockIdx.z;
    int cnt = g_cnt[e];
    int m0 = blockIdx.y * 64;
    if (m0 >= cnt) return;
    int n0 = blockIdx.x * 128;

    __shared__ __align__(16) float sA[2][16][APAD];
    __shared__ __align__(16) float sB[2][16][128];
    __shared__ int   stok[64];
    __shared__ float swt[64];

    int tid = threadIdx.x;
    int off = g_off[e];
    if (tid < 64) {
        int r = m0 + tid;
        int rr = r < cnt ? r : 0;
        stok[tid] = g_btok[e][rr];
        swt[tid]  = g_bw[e][rr];
    }
    __syncthreads();

    const float* Ap = g_act + (size_t)off * FFdim;
    const float* Bp = W_out + (size_t)e * FFdim * Hdim + n0;
    int tx = tid & 15, ty = tid >> 4;

    unsigned long long acc[8][4];
    #pragma unroll
    for (int i = 0; i < 8; i++)
        #pragma unroll
        for (int j = 0; j < 4; j++) acc[i][j] = 0ull;

    #pragma unroll
    for (int j = 0; j < 8; j++) {
        int i = tid + j * 128; int m = i >> 4, k = i & 15;
        int mm = (m0 + m < cnt) ? (m0 + m) : 0;
        sA[0][k][m] = Ap[(size_t)mm * FFdim + k];
    }
    #pragma unroll
    for (int j = 0; j < 4; j++) {
        int c = tid + j * 128; int k = c >> 5, n4 = c & 31;
        *(float4*)&sB[0][k][n4 * 4] =
            *(const float4*)&Bp[(size_t)k * Hdim + n4 * 4];
    }
    __syncthreads();

    float rA[8]; float4 rB[4];
    const int nK = FFdim / 16;
    for (int kt = 0; kt < nK; kt++) {
        int buf = kt & 1;
        if (kt + 1 < nK) {
            int kb = (kt + 1) * 16;
            #pragma unroll
            for (int j = 0; j < 8; j++) {
                int i = tid + j * 128; int m = i >> 4, k = i & 15;
                int mm = (m0 + m < cnt) ? (m0 + m) : 0;
                rA[j] = Ap[(size_t)mm * FFdim + kb + k];
            }
            #pragma unroll
            for (int j = 0; j < 4; j++) {
                int c = tid + j * 128; int k = c >> 5, n4 = c & 31;
                rB[j] = *(const float4*)&Bp[(size_t)(kb + k) * Hdim + n4 * 4];
            }
        }
        #pragma unroll
        for (int k = 0; k < 16; k++) {
            float4 a0 = *(const float4*)&sA[buf][k][ty * 8];
            float4 a1 = *(const float4*)&sA[buf][k][ty * 8 + 4];
            ulonglong2 b0 = *(const ulonglong2*)&sB[buf][k][tx * 4];
            ulonglong2 b1 = *(const ulonglong2*)&sB[buf][k][64 + tx * 4];
            unsigned long long bp[4] = {b0.x, b0.y, b1.x, b1.y};
            float av[8] = {a0.x, a0.y, a0.z, a0.w, a1.x, a1.y, a1.z, a1.w};
            #pragma unroll
            for (int i = 0; i < 8; i++) {
                unsigned long long ap; PACK2(ap, av[i]);
                #pragma unroll
                for (int j = 0; j < 4; j++) FMA2(acc[i][j], ap, bp[j]);
            }
        }
        if (kt + 1 < nK) {
            int nb = buf ^ 1;
            #pragma unroll
            for (int j = 0; j < 8; j++) {
                int i = tid + j * 128; int m = i >> 4, k = i & 15;
                sA[nb][k][m] = rA[j];
            }
            #pragma unroll
            for (int j = 0; j < 4; j++) {
                int c = tid + j * 128; int k = c >> 5, n4 = c & 31;
                *(float4*)&sB[nb][k][n4 * 4] = rB[j];
            }
        }
        __syncthreads();
    }

    const float* bo0 = b_out + (size_t)e * Hdim + n0 + tx * 4;
    const float* bo1 = bo0 + 64;
    #pragma unroll
    for (int i = 0; i < 8; i++) {
        int r = m0 + ty * 8 + i;
        if (r < cnt) {
            int tok = stok[ty * 8 + i];
            float w = swt[ty * 8 + i];
            float* d0 = out + (size_t)tok * Hdim + n0 + tx * 4;
            float* d1 = d0 + 64;
            atomicAdd(&d0[0], (lo32(acc[i][0]) + bo0[0]) * w);
            atomicAdd(&d0[1], (hi32(acc[i][0]) + bo0[1]) * w);
            atomicAdd(&d0[2], (lo32(acc[i][1]) + bo0[2]) * w);
            atomicAdd(&d0[3], (hi32(acc[i][1]) + bo0[3]) * w);
            atomicAdd(&d1[0], (lo32(acc[i][2]) + bo1[0]) * w);
            atomicAdd(&d1[1], (hi32(acc[i][2]) + bo1[1]) * w);
            atomicAdd(&d1[2], (lo32(acc[i][3]) + bo1[2]) * w);
            atomicAdd(&d1[3], (hi32(acc[i][3]) + bo1[3]) * w);
        }
    }
}

// ---------------- launcher ----------------
extern "C" void kernel_launch(void* const* d_in, const int* in_sizes, int n_in,
                              void* d_out, int out_size) {
    const float* x     = (const float*)d_in[0];
    const float* W_in  = (const float*)d_in[1];
    const float* b_in  = (const float*)d_in[2];
    const float* W_out = (const float*)d_in[3];
    const float* b_out = (const float*)d_in[4];
    const float* rw    = (const float*)d_in[5];
    const float* rb    = (const float*)d_in[6];
    float* out = (float*)d_out;

    k_zero<<<512, 256>>>(out, out_size);
    k_router<<<Stok, 128>>>(x, rw, rb);
    k_offsets<<<1, 32>>>(out, out_size);
    k_gemm1<<<dim3(FF2dim / 128, Stok / 64, Edim), 128>>>(x, W_in, b_in);
    k_act<<<2048, 256>>>();
    k_gemm2<<<dim3(Hdim / 128, Stok / 64, Edim), 128>>>(W_out, b_out, out);
}